// round 3
// baseline (speedup 1.0000x reference)
#include <cuda_runtime.h>

#define B_ 4
#define L_ 2048
#define D_ 1024
#define H_ 16
#define HD_ 64
#define M_ 8192

// ---------------- scratch (static device globals: allocation-free) ----------------
__device__ float g_h[M_ * D_];     // pre-LN output (also residual source)
__device__ float g_q[M_ * D_];     // [B*H][L][HD]
__device__ float g_k[M_ * D_];
__device__ float g_v[M_ * D_];
__device__ float g_att[M_ * D_];   // attention out, (B,L,D) row-major
__device__ float g_y[M_ * D_];     // o-proj + residual
__device__ unsigned char g_mask8[B_ * L_];

// ---------------- padding-mask canonicalization ----------------
// JAX bool may arrive as uint8 (1B) or int32/float32 (4B). A monotone-per-row
// uint8 bool mask with any padding yields packed words outside {0,1,0x3F800000};
// i32/f32 encodings yield only those values. Classify, then write uint8.
__global__ void mask_prep_kernel(const unsigned int* __restrict__ pw) {
    __shared__ int s_bad;
    if (threadIdx.x == 0) s_bad = 0;
    __syncthreads();
    int bad = 0;
    for (int i = threadIdx.x; i < (B_ * L_) / 4; i += blockDim.x) {
        unsigned v = pw[i];
        if (v != 0u && v != 1u && v != 0x3F800000u) bad = 1;
    }
    if (bad) atomicExch(&s_bad, 1);
    __syncthreads();
    if (s_bad) {  // uint8 layout
        const unsigned char* pb = (const unsigned char*)pw;
        for (int i = threadIdx.x; i < B_ * L_; i += blockDim.x)
            g_mask8[i] = pb[i] ? 1 : 0;
    } else {      // 4-byte layout (int32 or float32): word != 0 means padded
        for (int i = threadIdx.x; i < B_ * L_; i += blockDim.x)
            g_mask8[i] = pw[i] ? 1 : 0;
    }
}

// ---------------- LayerNorm (one block per row of 1024) ----------------
__global__ void ln_kernel(const float* __restrict__ x, const float* __restrict__ gamma,
                          const float* __restrict__ beta, float* __restrict__ out) {
    __shared__ float red[8];
    __shared__ float s_mu, s_rs;
    int row = blockIdx.x;
    int t = threadIdx.x;
    float4 v = ((const float4*)(x + (size_t)row * D_))[t];
    float s = v.x + v.y + v.z + v.w;
    #pragma unroll
    for (int o = 16; o; o >>= 1) s += __shfl_xor_sync(0xffffffffu, s, o);
    if ((t & 31) == 0) red[t >> 5] = s;
    __syncthreads();
    if (t == 0) {
        float tot = 0.f;
        #pragma unroll
        for (int i = 0; i < 8; i++) tot += red[i];
        s_mu = tot * (1.0f / D_);
    }
    __syncthreads();
    float mu = s_mu;
    float dx = v.x - mu, dy = v.y - mu, dz = v.z - mu, dw = v.w - mu;
    float ss = dx * dx + dy * dy + dz * dz + dw * dw;
    #pragma unroll
    for (int o = 16; o; o >>= 1) ss += __shfl_xor_sync(0xffffffffu, ss, o);
    __syncthreads();  // protect red[] reuse
    if ((t & 31) == 0) red[t >> 5] = ss;
    __syncthreads();
    if (t == 0) {
        float tot = 0.f;
        #pragma unroll
        for (int i = 0; i < 8; i++) tot += red[i];
        s_rs = rsqrtf(tot * (1.0f / D_) + 1e-5f);
    }
    __syncthreads();
    float rs = s_rs;
    float4 gv = ((const float4*)gamma)[t];
    float4 bv = ((const float4*)beta)[t];
    float4 o4;
    o4.x = dx * rs * gv.x + bv.x;
    o4.y = dy * rs * gv.y + bv.y;
    o4.z = dz * rs * gv.z + bv.z;
    o4.w = dw * rs * gv.w + bv.w;
    ((float4*)(out + (size_t)row * D_))[t] = o4;
}

// ---------------- NT SGEMM: C = A(MxK) * W(NxK)^T + bias ----------------
// heads_layout=1: scatter to [B*H][L][HD]. heads_layout=0: row-major + residual.
__global__ __launch_bounds__(256, 2) void sgemm_kernel(
    const float* __restrict__ A, const float* __restrict__ W,
    const float* __restrict__ bias, const float* __restrict__ res,
    float* __restrict__ C, int heads_layout) {
    __shared__ float As[8][128];
    __shared__ float Bs[8][128];
    int t = threadIdx.x;
    int m0 = blockIdx.y * 128, n0 = blockIdx.x * 128;
    int lr = t >> 1, lc = (t & 1) * 4;
    const float* Ap = A + (size_t)(m0 + lr) * D_ + lc;
    const float* Wp = W + (size_t)(n0 + lr) * D_ + lc;
    int tx = t & 15, ty = t >> 4;
    float acc[8][8];
    #pragma unroll
    for (int i = 0; i < 8; i++)
        #pragma unroll
        for (int j = 0; j < 8; j++) acc[i][j] = 0.f;

    for (int k0 = 0; k0 < D_; k0 += 8) {
        float4 av = *(const float4*)(Ap + k0);
        float4 bv = *(const float4*)(Wp + k0);
        As[lc + 0][lr] = av.x; As[lc + 1][lr] = av.y;
        As[lc + 2][lr] = av.z; As[lc + 3][lr] = av.w;
        Bs[lc + 0][lr] = bv.x; Bs[lc + 1][lr] = bv.y;
        Bs[lc + 2][lr] = bv.z; Bs[lc + 3][lr] = bv.w;
        __syncthreads();
        #pragma unroll
        for (int kk = 0; kk < 8; kk++) {
            float a[8], b[8];
            *(float4*)(a)     = *(const float4*)(&As[kk][ty * 8]);
            *(float4*)(a + 4) = *(const float4*)(&As[kk][ty * 8 + 4]);
            *(float4*)(b)     = *(const float4*)(&Bs[kk][tx * 8]);
            *(float4*)(b + 4) = *(const float4*)(&Bs[kk][tx * 8 + 4]);
            #pragma unroll
            for (int i = 0; i < 8; i++)
                #pragma unroll
                for (int j = 0; j < 8; j++)
                    acc[i][j] += a[i] * b[j];
        }
        __syncthreads();
    }

    int nb = n0 + tx * 8;
    float bb[8];
    *(float4*)(bb)     = *(const float4*)(bias + nb);
    *(float4*)(bb + 4) = *(const float4*)(bias + nb + 4);

    if (heads_layout) {
        int head = nb >> 6;
        int hd0 = nb & 63;  // 8 consecutive dims within one head
        #pragma unroll
        for (int i = 0; i < 8; i++) {
            int m = m0 + ty * 8 + i;
            int bidx = m >> 11, l = m & (L_ - 1);
            float* dst = C + ((size_t)(bidx * H_ + head) * L_ + l) * HD_ + hd0;
            float4 o0, o1;
            o0.x = acc[i][0] + bb[0]; o0.y = acc[i][1] + bb[1];
            o0.z = acc[i][2] + bb[2]; o0.w = acc[i][3] + bb[3];
            o1.x = acc[i][4] + bb[4]; o1.y = acc[i][5] + bb[5];
            o1.z = acc[i][6] + bb[6]; o1.w = acc[i][7] + bb[7];
            *(float4*)(dst)     = o0;
            *(float4*)(dst + 4) = o1;
        }
    } else {
        #pragma unroll
        for (int i = 0; i < 8; i++) {
            int m = m0 + ty * 8 + i;
            float4 r0 = *(const float4*)(res + (size_t)m * D_ + nb);
            float4 r1 = *(const float4*)(res + (size_t)m * D_ + nb + 4);
            float4 o0, o1;
            o0.x = acc[i][0] + bb[0] + r0.x; o0.y = acc[i][1] + bb[1] + r0.y;
            o0.z = acc[i][2] + bb[2] + r0.z; o0.w = acc[i][3] + bb[3] + r0.w;
            o1.x = acc[i][4] + bb[4] + r1.x; o1.y = acc[i][5] + bb[5] + r1.y;
            o1.z = acc[i][6] + bb[6] + r1.z; o1.w = acc[i][7] + bb[7] + r1.w;
            *(float4*)(C + (size_t)m * D_ + nb)     = o0;
            *(float4*)(C + (size_t)m * D_ + nb + 4) = o1;
        }
    }
}

// ---------------- Flash attention (fp32, online softmax) ----------------
// Block: (query tile of 64, b*h). 8 warps x 8 query rows. Lane <-> {key, key+32}
// for scores, lane <-> {dim, dim+32} for PV. Masks applied as -1e30 (exp -> 0).
__global__ void attn_kernel(const float* __restrict__ Q, const float* __restrict__ K,
                            const float* __restrict__ V, float* __restrict__ O) {
    extern __shared__ float sm[];
    float* Qs = sm;                 // [64][64]  (broadcast reads: no conflicts)
    float* Ks = Qs + 64 * 64;       // [64][65]  (odd stride: conflict-free key reads)
    float* Vs = Ks + 64 * 65;       // [64][65]
    float* Ps = Vs + 64 * 65;       // [8 warps][4 rows][64]

    int qt = gridDim.x - 1 - blockIdx.x;  // longest blocks first
    int bh = blockIdx.y;
    int bidx = bh >> 4;
    int t = threadIdx.x, w = t >> 5, lane = t & 31;

    const float* Qb = Q + ((size_t)bh * L_ + qt * 64) * HD_;
    #pragma unroll
    for (int i = 0; i < 4; i++) {
        int idx = i * 1024 + t * 4;
        int r = idx >> 6, d = idx & 63;
        float4 v = *(const float4*)(Qb + r * 64 + d);
        float4 sv; sv.x = v.x * 0.125f; sv.y = v.y * 0.125f;
        sv.z = v.z * 0.125f; sv.w = v.w * 0.125f;   // fold 1/sqrt(64)
        *(float4*)(Qs + r * 64 + d) = sv;
    }

    float mrow[8], lsum[8], acc0[8], acc1[8];
    #pragma unroll
    for (int i = 0; i < 8; i++) { mrow[i] = -1e30f; lsum[i] = 0.f; acc0[i] = 0.f; acc1[i] = 0.f; }

    for (int kt = 0; kt <= qt; kt++) {
        __syncthreads();  // previous tile fully consumed
        const float* Kb = K + ((size_t)bh * L_ + kt * 64) * HD_;
        const float* Vb = V + ((size_t)bh * L_ + kt * 64) * HD_;
        #pragma unroll
        for (int i = 0; i < 4; i++) {
            int idx = i * 1024 + t * 4;
            int r = idx >> 6, d = idx & 63;
            float4 kv = *(const float4*)(Kb + r * 64 + d);
            float* kp = Ks + r * 65 + d;
            kp[0] = kv.x; kp[1] = kv.y; kp[2] = kv.z; kp[3] = kv.w;
            float4 vv = *(const float4*)(Vb + r * 64 + d);
            float* vp = Vs + r * 65 + d;
            vp[0] = vv.x; vp[1] = vv.y; vp[2] = vv.z; vp[3] = vv.w;
        }
        __syncthreads();

        int kg0 = kt * 64 + lane, kg1 = kg0 + 32;
        bool ok0 = !g_mask8[bidx * L_ + kg0];
        bool ok1 = !g_mask8[bidx * L_ + kg1];

        #pragma unroll
        for (int g = 0; g < 2; g++) {
            int rbase = w * 8 + g * 4;
            float s0[4] = {0.f, 0.f, 0.f, 0.f}, s1[4] = {0.f, 0.f, 0.f, 0.f};
            #pragma unroll
            for (int d = 0; d < 64; d += 4) {
                float k00 = Ks[lane * 65 + d],     k01 = Ks[lane * 65 + d + 1];
                float k02 = Ks[lane * 65 + d + 2], k03 = Ks[lane * 65 + d + 3];
                float k10 = Ks[(lane + 32) * 65 + d],     k11 = Ks[(lane + 32) * 65 + d + 1];
                float k12 = Ks[(lane + 32) * 65 + d + 2], k13 = Ks[(lane + 32) * 65 + d + 3];
                #pragma unroll
                for (int r = 0; r < 4; r++) {
                    float4 qv = *(const float4*)(Qs + (rbase + r) * 64 + d);
                    s0[r] += qv.x * k00 + qv.y * k01 + qv.z * k02 + qv.w * k03;
                    s1[r] += qv.x * k10 + qv.y * k11 + qv.z * k12 + qv.w * k13;
                }
            }
            #pragma unroll
            for (int r = 0; r < 4; r++) {
                int li = g * 4 + r;
                int lq = qt * 64 + rbase + r;
                float v0 = (kg0 <= lq && ok0) ? s0[r] : -1e30f;
                float v1 = (kg1 <= lq && ok1) ? s1[r] : -1e30f;
                float tm = fmaxf(v0, v1);
                #pragma unroll
                for (int o = 16; o; o >>= 1) tm = fmaxf(tm, __shfl_xor_sync(0xffffffffu, tm, o));
                float newm = fmaxf(mrow[li], tm);
                float sc = __expf(mrow[li] - newm);
                float p0 = __expf(v0 - newm);
                float p1 = __expf(v1 - newm);
                float ps = p0 + p1;
                #pragma unroll
                for (int o = 16; o; o >>= 1) ps += __shfl_xor_sync(0xffffffffu, ps, o);
                mrow[li] = newm;
                lsum[li] = lsum[li] * sc + ps;
                acc0[li] *= sc; acc1[li] *= sc;
                Ps[(w * 4 + r) * 64 + lane] = p0;
                Ps[(w * 4 + r) * 64 + lane + 32] = p1;
            }
            __syncwarp();
            #pragma unroll 4
            for (int m4 = 0; m4 < 64; m4 += 4) {
                float p0a[4], p1a[4], p2a[4], p3a[4];
                *(float4*)p0a = *(const float4*)(Ps + (w * 4 + 0) * 64 + m4);
                *(float4*)p1a = *(const float4*)(Ps + (w * 4 + 1) * 64 + m4);
                *(float4*)p2a = *(const float4*)(Ps + (w * 4 + 2) * 64 + m4);
                *(float4*)p3a = *(const float4*)(Ps + (w * 4 + 3) * 64 + m4);
                #pragma unroll
                for (int j = 0; j < 4; j++) {
                    float vv0 = Vs[(m4 + j) * 65 + lane];
                    float vv1 = Vs[(m4 + j) * 65 + lane + 32];
                    acc0[g * 4 + 0] += p0a[j] * vv0;  acc1[g * 4 + 0] += p0a[j] * vv1;
                    acc0[g * 4 + 1] += p1a[j] * vv0;  acc1[g * 4 + 1] += p1a[j] * vv1;
                    acc0[g * 4 + 2] += p2a[j] * vv0;  acc1[g * 4 + 2] += p2a[j] * vv1;
                    acc0[g * 4 + 3] += p3a[j] * vv0;  acc1[g * 4 + 3] += p3a[j] * vv1;
                }
            }
            __syncwarp();
        }
    }

    int head = bh & (H_ - 1);
    #pragma unroll
    for (int li = 0; li < 8; li++) {
        int lq = qt * 64 + w * 8 + li;
        size_t m = (size_t)bidx * L_ + lq;
        float inv = 1.0f / lsum[li];
        float* dst = O + m * D_ + head * HD_;
        dst[lane]      = acc0[li] * inv;
        dst[lane + 32] = acc1[li] * inv;
    }
}

// ---------------- launch ----------------
extern "C" void kernel_launch(void* const* d_in, const int* in_sizes, int n_in,
                              void* d_out, int out_size) {
    const float* x     = (const float*)d_in[0];
    const void*  pmask = d_in[1];
    // d_in[2] = causal_mask (unused: causality applied analytically)
    const float* Wq = (const float*)d_in[3];
    const float* bq = (const float*)d_in[4];
    const float* Wk = (const float*)d_in[5];
    const float* bk = (const float*)d_in[6];
    const float* Wv = (const float*)d_in[7];
    const float* bv = (const float*)d_in[8];
    const float* Wo = (const float*)d_in[9];
    const float* bo = (const float*)d_in[10];
    const float* g_pre = (const float*)d_in[11];
    const float* b_pre = (const float*)d_in[12];
    const float* g_ln  = (const float*)d_in[13];
    const float* b_ln  = (const float*)d_in[14];
    float* out = (float*)d_out;

    float *h, *q, *k, *v, *att, *y;
    cudaGetSymbolAddress((void**)&h,   g_h);
    cudaGetSymbolAddress((void**)&q,   g_q);
    cudaGetSymbolAddress((void**)&k,   g_k);
    cudaGetSymbolAddress((void**)&v,   g_v);
    cudaGetSymbolAddress((void**)&att, g_att);
    cudaGetSymbolAddress((void**)&y,   g_y);

    const int attn_smem = (64 * 64 + 64 * 65 + 64 * 65 + 8 * 4 * 64) * (int)sizeof(float);
    cudaFuncSetAttribute(attn_kernel, cudaFuncAttributeMaxDynamicSharedMemorySize, attn_smem);

    mask_prep_kernel<<<1, 256>>>((const unsigned int*)pmask);
    ln_kernel<<<M_, 256>>>(x, g_pre, b_pre, h);

    dim3 ggrid(D_ / 128, M_ / 128);
    sgemm_kernel<<<ggrid, 256>>>(h, Wq, bq, nullptr, q, 1);
    sgemm_kernel<<<ggrid, 256>>>(h, Wk, bk, nullptr, k, 1);
    sgemm_kernel<<<ggrid, 256>>>(h, Wv, bv, nullptr, v, 1);

    attn_kernel<<<dim3(L_ / 64, B_ * H_), 256, attn_smem>>>(q, k, v, att);

    sgemm_kernel<<<ggrid, 256>>>(att, Wo, bo, h, y, 0);
    ln_kernel<<<M_, 256>>>(y, g_ln, b_ln, out);
}

// round 4
// speedup vs baseline: 3.9315x; 3.9315x over previous
#include <cuda_runtime.h>
#include <cstdint>

#define B_ 4
#define L_ 2048
#define D_ 1024
#define H_ 16
#define HD_ 64
#define M_ 8192

// ---------------- scratch ----------------
__device__ float g_h[M_ * D_];      // pre-LN output (tf32-rounded), residual source
__device__ float g_q[M_ * D_];      // [B*H][L][HD], tf32
__device__ float g_k[M_ * D_];
__device__ float g_v[M_ * D_];
__device__ float g_att[M_ * D_];    // attention out (B,L,D), tf32
__device__ float g_y[M_ * D_];      // o-proj + residual (fp32)
__device__ float g_wq4[D_ * D_];    // tf32-rounded weights
__device__ float g_wk4[D_ * D_];
__device__ float g_wv4[D_ * D_];
__device__ float g_wo4[D_ * D_];
__device__ int   g_len[B_];

// ---------------- helpers ----------------
__device__ __forceinline__ float tf32r(float x) {
    float y; asm("cvt.rna.tf32.f32 %0, %1;" : "=f"(y) : "f"(x)); return y;
}
#define CPA16(dst, src) asm volatile("cp.async.cg.shared.global [%0], [%1], 16;\n" ::"r"(dst), "l"(src))
#define CPA_COMMIT asm volatile("cp.async.commit_group;\n")

__device__ __forceinline__ void mma_tf32(float& c0, float& c1, float& c2, float& c3,
                                         uint32_t a0, uint32_t a1, uint32_t a2, uint32_t a3,
                                         uint32_t b0, uint32_t b1) {
    asm volatile(
        "mma.sync.aligned.m16n8k8.row.col.f32.tf32.tf32.f32 "
        "{%0,%1,%2,%3}, {%4,%5,%6,%7}, {%8,%9}, {%0,%1,%2,%3};\n"
        : "+f"(c0), "+f"(c1), "+f"(c2), "+f"(c3)
        : "r"(a0), "r"(a1), "r"(a2), "r"(a3), "r"(b0), "r"(b1));
}

// ---------------- mask -> lengths (monotone per spec) ----------------
__global__ void mask_len_kernel(const unsigned int* __restrict__ pw) {
    __shared__ int s_bad;
    int t = threadIdx.x;
    if (t == 0) s_bad = 0;
    if (t < B_) g_len[t] = L_;
    __syncthreads();
    int bad = 0;
    for (int i = t; i < (B_ * L_) / 4; i += 256) {
        unsigned v = pw[i];
        if (v != 0u && v != 1u && v != 0x3F800000u) bad = 1;
    }
    if (bad) atomicExch(&s_bad, 1);
    __syncthreads();
    if (s_bad) {  // uint8 layout
        const unsigned char* pb = (const unsigned char*)pw;
        for (int i = t; i < B_ * L_; i += 256)
            if (pb[i]) atomicMin(&g_len[i >> 11], i & (L_ - 1));
    } else {      // 32-bit layout
        for (int i = t; i < B_ * L_; i += 256)
            if (pw[i]) atomicMin(&g_len[i >> 11], i & (L_ - 1));
    }
}

// ---------------- weight tf32 pre-round ----------------
__global__ void wround_kernel(const float* __restrict__ a, const float* __restrict__ b,
                              const float* __restrict__ c, const float* __restrict__ d) {
    int i = blockIdx.x * 256 + threadIdx.x;
    g_wq4[i] = tf32r(a[i]);
    g_wk4[i] = tf32r(b[i]);
    g_wv4[i] = tf32r(c[i]);
    g_wo4[i] = tf32r(d[i]);
}

// ---------------- LayerNorm ----------------
__global__ void ln_kernel(const float* __restrict__ x, const float* __restrict__ gamma,
                          const float* __restrict__ beta, float* __restrict__ out, int rnd) {
    __shared__ float red[8];
    __shared__ float s_mu, s_rs;
    int row = blockIdx.x;
    int t = threadIdx.x;
    float4 v = ((const float4*)(x + (size_t)row * D_))[t];
    float s = v.x + v.y + v.z + v.w;
    #pragma unroll
    for (int o = 16; o; o >>= 1) s += __shfl_xor_sync(0xffffffffu, s, o);
    if ((t & 31) == 0) red[t >> 5] = s;
    __syncthreads();
    if (t == 0) {
        float tot = 0.f;
        #pragma unroll
        for (int i = 0; i < 8; i++) tot += red[i];
        s_mu = tot * (1.0f / D_);
    }
    __syncthreads();
    float mu = s_mu;
    float dx = v.x - mu, dy = v.y - mu, dz = v.z - mu, dw = v.w - mu;
    float ss = dx * dx + dy * dy + dz * dz + dw * dw;
    #pragma unroll
    for (int o = 16; o; o >>= 1) ss += __shfl_xor_sync(0xffffffffu, ss, o);
    __syncthreads();
    if ((t & 31) == 0) red[t >> 5] = ss;
    __syncthreads();
    if (t == 0) {
        float tot = 0.f;
        #pragma unroll
        for (int i = 0; i < 8; i++) tot += red[i];
        s_rs = rsqrtf(tot * (1.0f / D_) + 1e-5f);
    }
    __syncthreads();
    float rs = s_rs;
    float4 gv = ((const float4*)gamma)[t];
    float4 bv = ((const float4*)beta)[t];
    float4 o4;
    o4.x = dx * rs * gv.x + bv.x;
    o4.y = dy * rs * gv.y + bv.y;
    o4.z = dz * rs * gv.z + bv.z;
    o4.w = dw * rs * gv.w + bv.w;
    if (rnd) { o4.x = tf32r(o4.x); o4.y = tf32r(o4.y); o4.z = tf32r(o4.z); o4.w = tf32r(o4.w); }
    ((float4*)(out + (size_t)row * D_))[t] = o4;
}

// ---------------- tf32 tensor-core GEMM: C = A(MxK) x W(NxK)^T + bias ----------------
// Block 128(m) x 256(n), BK=32, 8 warps as 2x4 of 64x64 warp tiles.
// mode 1: scatter to [B*H][L][HD] + tf32 round.  mode 0: row-major + residual.
#define BK_ 32
#define AST 36   // BK + 4 pad  (stride % 32 == 4 -> conflict-free frag LDS)
__global__ __launch_bounds__(256, 1) void tgemm_kernel(
    const float* __restrict__ A, const float* __restrict__ W,
    const float* __restrict__ bias, const float* __restrict__ res,
    float* __restrict__ C, int mode) {
    extern __shared__ float sm[];
    float* As = sm;                   // [2][128][36]
    float* Bs = sm + 2 * 128 * AST;   // [2][256][36]
    int t = threadIdx.x, w = t >> 5, lane = t & 31;
    int r = lane >> 2, c4 = lane & 3;
    int m0 = blockIdx.y * 128, n0 = blockIdx.x * 256;
    int wm = w >> 2, wn = w & 3;

    float acc[4][8][4] = {};

    auto load_stage = [&](int st, int k0) {
        uint32_t sa = (uint32_t)__cvta_generic_to_shared(As + st * 128 * AST);
        uint32_t sb = (uint32_t)__cvta_generic_to_shared(Bs + st * 256 * AST);
        #pragma unroll
        for (int i = 0; i < 12; i++) {
            int cid = t + i * 256;
            if (cid < 1024) {
                int row = cid >> 3, kc = (cid & 7) * 4;
                CPA16(sa + (row * AST + kc) * 4, A + (size_t)(m0 + row) * D_ + k0 + kc);
            } else {
                int c2 = cid - 1024;
                int row = c2 >> 3, kc = (c2 & 7) * 4;
                CPA16(sb + (row * AST + kc) * 4, W + (size_t)(n0 + row) * D_ + k0 + kc);
            }
        }
    };

    load_stage(0, 0);
    CPA_COMMIT;
    #pragma unroll 1
    for (int kb = 0; kb < D_ / BK_; kb++) {
        if (kb + 1 < D_ / BK_) {
            load_stage((kb + 1) & 1, (kb + 1) * BK_);
            CPA_COMMIT;
            asm volatile("cp.async.wait_group 1;\n");
        } else {
            asm volatile("cp.async.wait_group 0;\n");
        }
        __syncthreads();
        const float* as = As + (kb & 1) * 128 * AST + (wm * 64) * AST;
        const float* bs = Bs + (kb & 1) * 256 * AST + (wn * 64) * AST;
        #pragma unroll
        for (int ks = 0; ks < 4; ks++) {
            int kk = ks * 8;
            uint32_t af[4][4], bf[8][2];
            #pragma unroll
            for (int mt = 0; mt < 4; mt++) {
                const float* p = as + (mt * 16 + r) * AST + kk + c4;
                af[mt][0] = __float_as_uint(p[0]);
                af[mt][1] = __float_as_uint(p[8 * AST]);
                af[mt][2] = __float_as_uint(p[4]);
                af[mt][3] = __float_as_uint(p[8 * AST + 4]);
            }
            #pragma unroll
            for (int nt = 0; nt < 8; nt++) {
                const float* p = bs + (nt * 8 + r) * AST + kk + c4;
                bf[nt][0] = __float_as_uint(p[0]);
                bf[nt][1] = __float_as_uint(p[4]);
            }
            #pragma unroll
            for (int mt = 0; mt < 4; mt++)
                #pragma unroll
                for (int nt = 0; nt < 8; nt++)
                    mma_tf32(acc[mt][nt][0], acc[mt][nt][1], acc[mt][nt][2], acc[mt][nt][3],
                             af[mt][0], af[mt][1], af[mt][2], af[mt][3],
                             bf[nt][0], bf[nt][1]);
        }
        __syncthreads();
    }

    int mrow = m0 + wm * 64, ncol = n0 + wn * 64;
    if (mode == 1) {
        #pragma unroll
        for (int mt = 0; mt < 4; mt++) {
            int row0 = mrow + mt * 16 + r;
            int bidx = row0 >> 11, l = row0 & (L_ - 1);
            #pragma unroll
            for (int nt = 0; nt < 8; nt++) {
                int col = ncol + nt * 8 + 2 * c4;
                int head = col >> 6, hd = col & 63;
                float b0 = bias[col], b1 = bias[col + 1];
                float* d0 = C + ((size_t)(bidx * H_ + head) * L_ + l) * HD_ + hd;
                float* d1 = C + ((size_t)(bidx * H_ + head) * L_ + l + 8) * HD_ + hd;
                float2 v0 = {tf32r(acc[mt][nt][0] + b0), tf32r(acc[mt][nt][1] + b1)};
                float2 v1 = {tf32r(acc[mt][nt][2] + b0), tf32r(acc[mt][nt][3] + b1)};
                *(float2*)d0 = v0;
                *(float2*)d1 = v1;
            }
        }
    } else {
        #pragma unroll
        for (int mt = 0; mt < 4; mt++) {
            int row0 = mrow + mt * 16 + r;
            #pragma unroll
            for (int nt = 0; nt < 8; nt++) {
                int col = ncol + nt * 8 + 2 * c4;
                float b0 = bias[col], b1 = bias[col + 1];
                float2 r0 = *(const float2*)(res + (size_t)row0 * D_ + col);
                float2 r1 = *(const float2*)(res + (size_t)(row0 + 8) * D_ + col);
                float2 v0 = {acc[mt][nt][0] + b0 + r0.x, acc[mt][nt][1] + b1 + r0.y};
                float2 v1 = {acc[mt][nt][2] + b0 + r1.x, acc[mt][nt][3] + b1 + r1.y};
                *(float2*)(C + (size_t)row0 * D_ + col) = v0;
                *(float2*)(C + (size_t)(row0 + 8) * D_ + col) = v1;
            }
        }
    }
}

// ---------------- tf32 tensor-core flash attention ----------------
// 128 query rows per block, 8 warps x 16 rows, K-tile 64, cp.async double-buffered.
#define KSTR 68   // % 32 == 4
#define VSTR 72   // % 32 == 8
#define PSTR 68
__global__ __launch_bounds__(256, 1) void attn_tc_kernel(
    const float* __restrict__ Q, const float* __restrict__ K,
    const float* __restrict__ V, float* __restrict__ O) {
    extern __shared__ float sm[];
    float* Ks = sm;                       // [2][64][68]
    float* Vs = Ks + 2 * 64 * KSTR;       // [2][64][72]
    float* Ps = Vs + 2 * 64 * VSTR;       // [8][16][68]
    int t = threadIdx.x, w = t >> 5, lane = t & 31;
    int r = lane >> 2, c4 = lane & 3;
    int qt = gridDim.x - 1 - blockIdx.x;  // longest first
    int bh = blockIdx.y;
    int bidx = bh >> 4, head = bh & (H_ - 1);
    int len = g_len[bidx];
    int qbase = qt * 128;
    int gqw = qbase + w * 16;             // warp's first query row

    // Q fragments register-resident (scale 0.125 = 2^-3, preserves tf32)
    const float* Qb = Q + ((size_t)bh * L_ + gqw) * HD_;
    uint32_t qa[8][4];
    #pragma unroll
    for (int ks = 0; ks < 8; ks++) {
        qa[ks][0] = __float_as_uint(Qb[r * 64 + ks * 8 + c4] * 0.125f);
        qa[ks][1] = __float_as_uint(Qb[(r + 8) * 64 + ks * 8 + c4] * 0.125f);
        qa[ks][2] = __float_as_uint(Qb[r * 64 + ks * 8 + c4 + 4] * 0.125f);
        qa[ks][3] = __float_as_uint(Qb[(r + 8) * 64 + ks * 8 + c4 + 4] * 0.125f);
    }

    float o_[8][4] = {};
    float m0v = -1e30f, m1v = -1e30f, l0 = 0.f, l1 = 0.f;
    float* pw = Ps + w * 16 * PSTR;
    int nkt = qt * 2 + 2;

    auto load_stage = [&](int st, int kt2) {
        const float* Kb = K + ((size_t)bh * L_ + kt2 * 64) * HD_;
        const float* Vb = V + ((size_t)bh * L_ + kt2 * 64) * HD_;
        uint32_t sk = (uint32_t)__cvta_generic_to_shared(Ks + st * 64 * KSTR);
        uint32_t sv = (uint32_t)__cvta_generic_to_shared(Vs + st * 64 * VSTR);
        #pragma unroll
        for (int i = 0; i < 4; i++) {
            int cid = t + i * 256;
            int row = cid >> 4, kc = (cid & 15) * 4;
            CPA16(sk + (row * KSTR + kc) * 4, Kb + row * 64 + kc);
        }
        #pragma unroll
        for (int i = 0; i < 4; i++) {
            int cid = t + i * 256;
            int row = cid >> 4, kc = (cid & 15) * 4;
            CPA16(sv + (row * VSTR + kc) * 4, Vb + row * 64 + kc);
        }
    };

    load_stage(0, 0);
    CPA_COMMIT;
    #pragma unroll 1
    for (int kt = 0; kt < nkt; kt++) {
        if (kt + 1 < nkt) {
            load_stage((kt + 1) & 1, kt + 1);
            CPA_COMMIT;
            asm volatile("cp.async.wait_group 1;\n");
        } else {
            asm volatile("cp.async.wait_group 0;\n");
        }
        __syncthreads();
        int kbase = kt * 64;
        if (kbase <= gqw + 15 && kbase < len) {
            const float* ks_ = Ks + (kt & 1) * 64 * KSTR;
            const float* vs_ = Vs + (kt & 1) * 64 * VSTR;
            // S = Q K^T  (16 x 64 per warp)
            float s[8][4] = {};
            #pragma unroll
            for (int ks = 0; ks < 8; ks++) {
                uint32_t bf[8][2];
                #pragma unroll
                for (int nt = 0; nt < 8; nt++) {
                    const float* p = ks_ + (nt * 8 + r) * KSTR + ks * 8 + c4;
                    bf[nt][0] = __float_as_uint(p[0]);
                    bf[nt][1] = __float_as_uint(p[4]);
                }
                #pragma unroll
                for (int nt = 0; nt < 8; nt++)
                    mma_tf32(s[nt][0], s[nt][1], s[nt][2], s[nt][3],
                             qa[ks][0], qa[ks][1], qa[ks][2], qa[ks][3],
                             bf[nt][0], bf[nt][1]);
            }
            // masking (length + causal); skip when tile fully valid for whole warp
            int gq0 = gqw + r, gq1 = gq0 + 8;
            bool full = (kbase + 63 <= gqw) && (kbase + 64 <= len);
            if (!full) {
                #pragma unroll
                for (int nt = 0; nt < 8; nt++) {
                    int kc = kbase + nt * 8 + 2 * c4;
                    if (!(kc     <= gq0 && kc     < len)) s[nt][0] = -1e30f;
                    if (!(kc + 1 <= gq0 && kc + 1 < len)) s[nt][1] = -1e30f;
                    if (!(kc     <= gq1 && kc     < len)) s[nt][2] = -1e30f;
                    if (!(kc + 1 <= gq1 && kc + 1 < len)) s[nt][3] = -1e30f;
                }
            }
            // online softmax (rows r, r+8 per thread; quad = same row)
            float mx0 = -1e30f, mx1 = -1e30f;
            #pragma unroll
            for (int nt = 0; nt < 8; nt++) {
                mx0 = fmaxf(mx0, fmaxf(s[nt][0], s[nt][1]));
                mx1 = fmaxf(mx1, fmaxf(s[nt][2], s[nt][3]));
            }
            mx0 = fmaxf(mx0, __shfl_xor_sync(0xffffffffu, mx0, 1));
            mx0 = fmaxf(mx0, __shfl_xor_sync(0xffffffffu, mx0, 2));
            mx1 = fmaxf(mx1, __shfl_xor_sync(0xffffffffu, mx1, 1));
            mx1 = fmaxf(mx1, __shfl_xor_sync(0xffffffffu, mx1, 2));
            float nm0 = fmaxf(m0v, mx0), nm1 = fmaxf(m1v, mx1);
            float sc0 = __expf(m0v - nm0), sc1 = __expf(m1v - nm1);
            m0v = nm0; m1v = nm1;
            float rs0 = 0.f, rs1 = 0.f;
            #pragma unroll
            for (int nt = 0; nt < 8; nt++) {
                s[nt][0] = __expf(s[nt][0] - nm0); rs0 += s[nt][0];
                s[nt][1] = __expf(s[nt][1] - nm0); rs0 += s[nt][1];
                s[nt][2] = __expf(s[nt][2] - nm1); rs1 += s[nt][2];
                s[nt][3] = __expf(s[nt][3] - nm1); rs1 += s[nt][3];
            }
            rs0 += __shfl_xor_sync(0xffffffffu, rs0, 1);
            rs0 += __shfl_xor_sync(0xffffffffu, rs0, 2);
            rs1 += __shfl_xor_sync(0xffffffffu, rs1, 1);
            rs1 += __shfl_xor_sync(0xffffffffu, rs1, 2);
            l0 = l0 * sc0 + rs0;
            l1 = l1 * sc1 + rs1;
            #pragma unroll
            for (int nt = 0; nt < 8; nt++) {
                o_[nt][0] *= sc0; o_[nt][1] *= sc0;
                o_[nt][2] *= sc1; o_[nt][3] *= sc1;
                float2 p0 = {tf32r(s[nt][0]), tf32r(s[nt][1])};
                float2 p1 = {tf32r(s[nt][2]), tf32r(s[nt][3])};
                *(float2*)(pw + r * PSTR + nt * 8 + 2 * c4) = p0;
                *(float2*)(pw + (r + 8) * PSTR + nt * 8 + 2 * c4) = p1;
            }
            __syncwarp();
            // O += P V   (k = 64 keys)
            #pragma unroll
            for (int ks = 0; ks < 8; ks++) {
                uint32_t a0 = __float_as_uint(pw[r * PSTR + ks * 8 + c4]);
                uint32_t a1 = __float_as_uint(pw[(r + 8) * PSTR + ks * 8 + c4]);
                uint32_t a2 = __float_as_uint(pw[r * PSTR + ks * 8 + c4 + 4]);
                uint32_t a3 = __float_as_uint(pw[(r + 8) * PSTR + ks * 8 + c4 + 4]);
                #pragma unroll
                for (int nt = 0; nt < 8; nt++) {
                    uint32_t b0 = __float_as_uint(vs_[(ks * 8 + c4) * VSTR + nt * 8 + r]);
                    uint32_t b1 = __float_as_uint(vs_[(ks * 8 + c4 + 4) * VSTR + nt * 8 + r]);
                    mma_tf32(o_[nt][0], o_[nt][1], o_[nt][2], o_[nt][3],
                             a0, a1, a2, a3, b0, b1);
                }
            }
            __syncwarp();
        }
        __syncthreads();
    }

    float inv0 = 1.0f / l0, inv1 = 1.0f / l1;
    size_t ob = (size_t)bidx * L_ + gqw;
    #pragma unroll
    for (int nt = 0; nt < 8; nt++) {
        int col = head * HD_ + nt * 8 + 2 * c4;
        float2 v0 = {tf32r(o_[nt][0] * inv0), tf32r(o_[nt][1] * inv0)};
        float2 v1 = {tf32r(o_[nt][2] * inv1), tf32r(o_[nt][3] * inv1)};
        *(float2*)(O + (ob + r) * D_ + col) = v0;
        *(float2*)(O + (ob + r + 8) * D_ + col) = v1;
    }
}

// ---------------- launch ----------------
extern "C" void kernel_launch(void* const* d_in, const int* in_sizes, int n_in,
                              void* d_out, int out_size) {
    const float* x     = (const float*)d_in[0];
    const void*  pmask = d_in[1];
    const float* Wq = (const float*)d_in[3];
    const float* bq = (const float*)d_in[4];
    const float* Wk = (const float*)d_in[5];
    const float* bk = (const float*)d_in[6];
    const float* Wv = (const float*)d_in[7];
    const float* bv = (const float*)d_in[8];
    const float* Wo = (const float*)d_in[9];
    const float* bo = (const float*)d_in[10];
    const float* g_pre = (const float*)d_in[11];
    const float* b_pre = (const float*)d_in[12];
    const float* g_ln  = (const float*)d_in[13];
    const float* b_ln  = (const float*)d_in[14];
    float* out = (float*)d_out;

    float *h, *q, *k, *v, *att, *y, *wq4, *wk4, *wv4, *wo4;
    cudaGetSymbolAddress((void**)&h,   g_h);
    cudaGetSymbolAddress((void**)&q,   g_q);
    cudaGetSymbolAddress((void**)&k,   g_k);
    cudaGetSymbolAddress((void**)&v,   g_v);
    cudaGetSymbolAddress((void**)&att, g_att);
    cudaGetSymbolAddress((void**)&y,   g_y);
    cudaGetSymbolAddress((void**)&wq4, g_wq4);
    cudaGetSymbolAddress((void**)&wk4, g_wk4);
    cudaGetSymbolAddress((void**)&wv4, g_wv4);
    cudaGetSymbolAddress((void**)&wo4, g_wo4);

    const int gemm_smem = 2 * (128 + 256) * AST * (int)sizeof(float);                 // 110592
    const int attn_smem = (2 * 64 * KSTR + 2 * 64 * VSTR + 8 * 16 * PSTR) * (int)sizeof(float);
    cudaFuncSetAttribute(tgemm_kernel,  cudaFuncAttributeMaxDynamicSharedMemorySize, gemm_smem);
    cudaFuncSetAttribute(attn_tc_kernel, cudaFuncAttributeMaxDynamicSharedMemorySize, attn_smem);

    mask_len_kernel<<<1, 256>>>((const unsigned int*)pmask);
    wround_kernel<<<(D_ * D_) / 256, 256>>>(Wq, Wk, Wv, Wo);
    ln_kernel<<<M_, 256>>>(x, g_pre, b_pre, h, 1);

    dim3 ggrid(D_ / 256, M_ / 128);
    tgemm_kernel<<<ggrid, 256, gemm_smem>>>(h, wq4, bq, nullptr, q, 1);
    tgemm_kernel<<<ggrid, 256, gemm_smem>>>(h, wk4, bk, nullptr, k, 1);
    tgemm_kernel<<<ggrid, 256, gemm_smem>>>(h, wv4, bv, nullptr, v, 1);

    attn_tc_kernel<<<dim3(L_ / 128, B_ * H_), 256, attn_smem>>>(q, k, v, att);

    tgemm_kernel<<<ggrid, 256, gemm_smem>>>(att, wo4, bo, h, y, 0);
    ln_kernel<<<M_, 256>>>(y, g_ln, b_ln, out, 0);
}